// round 15
// baseline (speedup 1.0000x reference)
#include <cuda_runtime.h>
#include <cuda_bf16.h>
#include <math.h>
#include <stdint.h>

#define Bb 128
#define Tt 64
#define Ee 768
#define Hh 768
#define Gg 3072
#define NCTA 128
#define WPAD 772
#define HPAD2 132                     // h staging row stride (words), 128-word chunks
#define WQ (48 * WPAD)                // 37,056 words: W shard
#define HSBUF (64 * HPAD2)            // 8,448 words per h buffer
#define HSOFF WQ
#define CRES (WQ + 2 * HSBUF)         // resident c (768 floats)
#define SMEMW (CRES + Hh)             // 54,720 words = 218,880 B

__device__ int      g_len[Bb];
__device__ int      g_nrows;
__device__ int      g_rows[Bb * Tt];
__device__ int      g_erow[Bb * Tt];
__device__ float    g_xproj[Tt * Bb * Gg];
__device__ uint32_t g_hpk[Bb * Hh];        // h packed: (lo_bf16<<16)|hi_bf16
__device__ float    g_gates[Bb * Gg];
__device__ unsigned g_bar2[1280];          // counters at 512B spacing: (bg*4+sh)*128; roots (8+bg)*128

__device__ __forceinline__ uint32_t pksplit(float v) {
    __nv_bfloat16 h = __float2bfloat16(v);
    float r = v - __bfloat162float(h);
    __nv_bfloat16 l = __float2bfloat16(r);
    return ((uint32_t)__bfloat16_as_ushort(l) << 16) | (uint32_t)__bfloat16_as_ushort(h);
}
#define HIPAIR(u0, u1) __byte_perm((u0), (u1), 0x5410)
#define LOPAIR(u0, u1) __byte_perm((u0), (u1), 0x7632)

__device__ __forceinline__ void mma16(float* c, const uint32_t* a, const uint32_t* b) {
    asm volatile("mma.sync.aligned.m16n8k16.row.col.f32.bf16.bf16.f32 "
        "{%0,%1,%2,%3}, {%4,%5,%6,%7}, {%8,%9}, {%0,%1,%2,%3};"
        : "+f"(c[0]), "+f"(c[1]), "+f"(c[2]), "+f"(c[3])
        : "r"(a[0]), "r"(a[1]), "r"(a[2]), "r"(a[3]), "r"(b[0]), "r"(b[1]));
}
__device__ __forceinline__ void cpa16(void* sdst, const void* g) {
    uint32_t sa = (uint32_t)__cvta_generic_to_shared(sdst);
    asm volatile("cp.async.cg.shared.global [%0], [%1], 16;" :: "r"(sa), "l"(g));
}

// fused LSTM cell: 5 EX2 + 2 RCP, branch-free, exact to fp32 rounding
__device__ __forceinline__ void cellop(float ig, float fg, float gg, float og,
                                       float c, float& cn, float& hr) {
    ig = fminf(fmaxf(ig, -25.f), 25.f);
    fg = fminf(fmaxf(fg, -25.f), 25.f);
    og = fminf(fmaxf(og, -25.f), 25.f);
    gg = fminf(fmaxf(gg, -12.5f), 12.5f);
    float A  = 1.f + __expf(-ig);
    float F  = 1.f + __expf(-fg);
    float eg = __expf(2.f * gg);
    float AG = A * (eg + 1.f);
    cn = __fdividef(c * AG + F * (eg - 1.f), F * AG);
    float cc = fminf(fmaxf(cn, -12.5f), 12.5f);
    float e2 = __expf(2.f * cc);
    hr = __fdividef(e2 - 1.f, (1.f + __expf(-og)) * (e2 + 1.f));
}

// ---------------- K0: dtype detect + setup (prefix-scan) ----
__global__ void k0_setup(const int* __restrict__ msg, const int* __restrict__ mlen) {
    __shared__ int s_flag;
    __shared__ int s_len[Bb];
    int tid = threadIdx.x;
    if (tid == 0) s_flag = 0;
    if (tid < 10) g_bar2[tid * 128] = 0;
    __syncthreads();
    int local = 0;
    for (int i = tid; i < (Bb * Tt) / 2; i += 256)
        if (msg[2 * i + 1] != 0) local = 1;
    if (local) atomicOr(&s_flag, 1);
    __syncthreads();
    int is64 = (s_flag == 0);
    if (tid < Bb) {
        int lb = is64 ? mlen[2 * tid] : mlen[tid];
        g_len[tid] = lb;
        s_len[tid] = lb;
    }
    __syncthreads();
    if (tid < Bb) {
        int base = 0;
        for (int i = 0; i < tid; i++) base += s_len[i];
        int lb = s_len[tid];
        for (int t = 0; t < lb; t++) {
            int r = base + t;
            g_rows[r] = (tid << 6) | t;
            int mi = tid * Tt + t;
            g_erow[r] = is64 ? msg[2 * mi] : msg[mi];
        }
        if (tid == Bb - 1) g_nrows = base + lb;
    }
}

// ---------------- K1: input projection, bf16x3 (proven) ----------
__global__ __launch_bounds__(256) void k1_xproj(const float* __restrict__ embt,
                                                const float* __restrict__ Wih,
                                                const float* __restrict__ bih) {
    __shared__ uint32_t As[128][36];
    __shared__ uint32_t Bs[64][36];
    __shared__ int s_bt[128];
    __shared__ int s_eoff[128];
    int tid = threadIdx.x;
    int nrows = g_nrows;
    int r0 = blockIdx.x * 128;
    if (r0 >= nrows) return;
    int n0 = blockIdx.y * 64;
    if (tid < 128) {
        int r = r0 + tid;
        if (r < nrows) { s_bt[tid] = g_rows[r]; s_eoff[tid] = g_erow[r] * Ee; }
        else           { s_bt[tid] = -1;        s_eoff[tid] = 0; }
    }
    const float* W1 = Wih + (size_t)Gg * Ee;
    int l = tid & 31, w = tid >> 5;
    int wm = w >> 1, wn = w & 1;
    float acc[2][4][4];
#pragma unroll
    for (int i = 0; i < 2; i++)
#pragma unroll
        for (int jn = 0; jn < 4; jn++)
#pragma unroll
            for (int q = 0; q < 4; q++) acc[i][jn][q] = 0.0f;
    int arow = tid >> 1, ak = (tid & 1) * 16;
    int brow = tid >> 2, bk = (tid & 3) * 8;
    for (int kk = 0; kk < Ee; kk += 32) {
        __syncthreads();
        const float* ap = embt + s_eoff[arow] + kk + ak;
#pragma unroll
        for (int i = 0; i < 4; i++) {
            float4 v = *(const float4*)(ap + 4 * i);
            As[arow][ak + 4 * i + 0] = pksplit(v.x);
            As[arow][ak + 4 * i + 1] = pksplit(v.y);
            As[arow][ak + 4 * i + 2] = pksplit(v.z);
            As[arow][ak + 4 * i + 3] = pksplit(v.w);
        }
        const float* bp = W1 + (size_t)(n0 + brow) * Ee + kk + bk;
#pragma unroll
        for (int i = 0; i < 2; i++) {
            float4 v = *(const float4*)(bp + 4 * i);
            Bs[brow][bk + 4 * i + 0] = pksplit(v.x);
            Bs[brow][bk + 4 * i + 1] = pksplit(v.y);
            Bs[brow][bk + 4 * i + 2] = pksplit(v.z);
            Bs[brow][bk + 4 * i + 3] = pksplit(v.w);
        }
        __syncthreads();
#pragma unroll
        for (int k16 = 0; k16 < 2; k16++) {
            int kp = k16 * 16 + (l & 3) * 2;
            uint32_t ahi[2][4], alo[2][4];
#pragma unroll
            for (int mt = 0; mt < 2; mt++) {
                int mb = wm * 32 + mt * 16 + (l >> 2);
                uint2 p0 = *(const uint2*)&As[mb][kp];
                uint2 p1 = *(const uint2*)&As[mb + 8][kp];
                uint2 p2 = *(const uint2*)&As[mb][kp + 8];
                uint2 p3 = *(const uint2*)&As[mb + 8][kp + 8];
                ahi[mt][0] = HIPAIR(p0.x, p0.y); alo[mt][0] = LOPAIR(p0.x, p0.y);
                ahi[mt][1] = HIPAIR(p1.x, p1.y); alo[mt][1] = LOPAIR(p1.x, p1.y);
                ahi[mt][2] = HIPAIR(p2.x, p2.y); alo[mt][2] = LOPAIR(p2.x, p2.y);
                ahi[mt][3] = HIPAIR(p3.x, p3.y); alo[mt][3] = LOPAIR(p3.x, p3.y);
            }
            uint32_t bhi[4][2], blo[4][2];
#pragma unroll
            for (int nt = 0; nt < 4; nt++) {
                int nb = wn * 32 + nt * 8 + (l >> 2);
                uint2 q0 = *(const uint2*)&Bs[nb][kp];
                uint2 q1 = *(const uint2*)&Bs[nb][kp + 8];
                bhi[nt][0] = HIPAIR(q0.x, q0.y); blo[nt][0] = LOPAIR(q0.x, q0.y);
                bhi[nt][1] = HIPAIR(q1.x, q1.y); blo[nt][1] = LOPAIR(q1.x, q1.y);
            }
#pragma unroll
            for (int mt = 0; mt < 2; mt++)
#pragma unroll
                for (int nt = 0; nt < 4; nt++) {
                    mma16(acc[mt][nt], ahi[mt], bhi[nt]);
                    mma16(acc[mt][nt], ahi[mt], blo[nt]);
                    mma16(acc[mt][nt], alo[mt], bhi[nt]);
                }
        }
    }
#pragma unroll
    for (int mt = 0; mt < 2; mt++) {
        int rbase = wm * 32 + mt * 16 + (l >> 2);
#pragma unroll
        for (int nt = 0; nt < 4; nt++) {
            int nc = n0 + wn * 32 + nt * 8 + 2 * (l & 3);
            float2 bias = *(const float2*)(bih + Gg + nc);
            int meta = s_bt[rbase];
            if (meta >= 0) {
                int b_ = meta >> 6, t_ = meta & 63;
                float2 o; o.x = acc[mt][nt][0] + bias.x; o.y = acc[mt][nt][1] + bias.y;
                *(float2*)(g_xproj + ((size_t)(t_ * Bb) + b_) * Gg + nc) = o;
            }
            meta = s_bt[rbase + 8];
            if (meta >= 0) {
                int b_ = meta >> 6, t_ = meta & 63;
                float2 o; o.x = acc[mt][nt][2] + bias.x; o.y = acc[mt][nt][3] + bias.y;
                *(float2*)(g_xproj + ((size_t)(t_ * Bb) + b_) * Gg + nc) = o;
            }
        }
    }
}

// ---------------- persistent recurrence ----------------
// hierarchical group barrier: 4 shard counters (16 arrivals each) + 1 root per group
__device__ __forceinline__ void gbar(int bg, int sh, unsigned epoch) {
    __syncthreads();
    if (threadIdx.x == 0) {
        __threadfence();
        unsigned old = atomicAdd(&g_bar2[(bg * 4 + sh) * 128], 1u);
        if (old == 16u * epoch - 1u) atomicAdd(&g_bar2[(8 + bg) * 128], 1u);
        volatile unsigned* root = &g_bar2[(8 + bg) * 128];
        while (*root < 4u * epoch) { __nanosleep(32); }
        __threadfence();
    }
    __syncthreads();
}

extern __shared__ uint32_t dsm[];

__global__ __launch_bounds__(256, 1) void krec(
        const float* __restrict__ Whh, const float* __restrict__ bhh,
        const float* __restrict__ gmh, const float* __restrict__ bth,
        const float* __restrict__ gmc, const float* __restrict__ btc,
        float* __restrict__ out) {
    uint32_t* w_sh = dsm;
    uint32_t* hs   = dsm + HSOFF;
    float* cellf   = (float*)(dsm + HSOFF);   // phase-B overlay of h staging
    float* c_res   = (float*)(dsm + CRES);    // resident cell state (this CTA's batch)

    int tid = threadIdx.x;
    int bg = blockIdx.x >> 6;
    int gidx = blockIdx.x & 63;
    int sh_id = gidx >> 4;
    int j = blockIdx.x;

    // Load W_hh[1] shard (packed bf16 hi/lo), once for all steps.
    const float* W1 = Whh + (size_t)Gg * Hh + (size_t)gidx * 48 * Hh;
    for (int i = tid; i < 48 * (Hh / 4); i += 256) {
        int n = i / (Hh / 4), kq = (i % (Hh / 4)) * 4;
        float4 v = *(const float4*)(W1 + (size_t)n * Hh + kq);
        uint32_t* d = &w_sh[n * WPAD + kq];
        d[0] = pksplit(v.x); d[1] = pksplit(v.y); d[2] = pksplit(v.z); d[3] = pksplit(v.w);
    }
    // zero resident c
    for (int i = tid; i < Hh; i += 256) c_res[i] = 0.0f;

    int l = tid & 31, w = tid >> 5;
    int wm = w >> 1, wn = w & 1;
    int srow = tid & 63, sq = (tid >> 6) * 32;
    const uint32_t* hsrc_base = g_hpk + (size_t)(bg * 64 + srow) * Hh + sq;
    uint32_t* sd0 = hs + srow * HPAD2 + sq;

    int r_  = wm * 16 + (l >> 2);
    int b0_ = bg * 64 + r_;
    int b1_ = b0_ + 8;
    int len_j = g_len[j];
    float2 bias[3];
#pragma unroll
    for (int nt = 0; nt < 3; nt++)
        bias[nt] = *(const float2*)(bhh + Gg + gidx * 48 + wn * 24 + nt * 8 + 2 * (l & 3));

    for (int t = 0; t < Tt; t++) {
        // prefetch xproj (independent of h)
        float2 xp0[3], xp1[3];
#pragma unroll
        for (int nt = 0; nt < 3; nt++) {
            int nc = gidx * 48 + wn * 24 + nt * 8 + 2 * (l & 3);
            xp0[nt] = *(const float2*)(g_xproj + ((size_t)(t * Bb) + b0_) * Gg + nc);
            xp1[nt] = *(const float2*)(g_xproj + ((size_t)(t * Bb) + b1_) * Gg + nc);
        }

        float acc[3][4];
#pragma unroll
        for (int i = 0; i < 3; i++)
#pragma unroll
            for (int q = 0; q < 4; q++) acc[i][q] = 0.0f;

        { // stage chunk 0: 32 words/thread = 8 x 16B cp.async
#pragma unroll
            for (int i = 0; i < 8; i++) cpa16(sd0 + 4 * i, hsrc_base + 4 * i);
            asm volatile("cp.async.commit_group;");
        }
#pragma unroll 1
        for (int c = 0; c < 6; c++) {
            if (c < 5) {
                const uint32_t* src = hsrc_base + (c + 1) * 128;
                uint32_t* dst = sd0 + ((c + 1) & 1) * HSBUF;
#pragma unroll
                for (int i = 0; i < 8; i++) cpa16(dst + 4 * i, src + 4 * i);
                asm volatile("cp.async.commit_group;");
                asm volatile("cp.async.wait_group 1;");
            } else {
                asm volatile("cp.async.wait_group 0;");
            }
            __syncthreads();
            const uint32_t* hb = hs + (c & 1) * HSBUF;
            int ar = wm * 16 + (l >> 2);
#pragma unroll
            for (int k16 = 0; k16 < 8; k16++) {
                int kp = k16 * 16 + (l & 3) * 2;
                uint32_t ahi[4], alo[4];
                {
                    uint2 p0 = *(const uint2*)&hb[ar * HPAD2 + kp];
                    uint2 p1 = *(const uint2*)&hb[(ar + 8) * HPAD2 + kp];
                    uint2 p2 = *(const uint2*)&hb[ar * HPAD2 + kp + 8];
                    uint2 p3 = *(const uint2*)&hb[(ar + 8) * HPAD2 + kp + 8];
                    ahi[0] = HIPAIR(p0.x, p0.y); alo[0] = LOPAIR(p0.x, p0.y);
                    ahi[1] = HIPAIR(p1.x, p1.y); alo[1] = LOPAIR(p1.x, p1.y);
                    ahi[2] = HIPAIR(p2.x, p2.y); alo[2] = LOPAIR(p2.x, p2.y);
                    ahi[3] = HIPAIR(p3.x, p3.y); alo[3] = LOPAIR(p3.x, p3.y);
                }
                int kg = c * 128 + kp;
#pragma unroll
                for (int nt = 0; nt < 3; nt++) {
                    int nr = wn * 24 + nt * 8 + (l >> 2);
                    uint2 q0 = *(const uint2*)&w_sh[nr * WPAD + kg];
                    uint2 q1 = *(const uint2*)&w_sh[nr * WPAD + kg + 8];
                    uint32_t bhi[2], blo[2];
                    bhi[0] = HIPAIR(q0.x, q0.y); blo[0] = LOPAIR(q0.x, q0.y);
                    bhi[1] = HIPAIR(q1.x, q1.y); blo[1] = LOPAIR(q1.x, q1.y);
                    mma16(acc[nt], ahi, bhi);
                    mma16(acc[nt], ahi, blo);
                    mma16(acc[nt], alo, bhi);
                }
            }
            __syncthreads();
        }
        // epilogue: store-only
#pragma unroll
        for (int nt = 0; nt < 3; nt++) {
            int nc = gidx * 48 + wn * 24 + nt * 8 + 2 * (l & 3);
            float2 o;
            o.x = acc[nt][0] + xp0[nt].x + bias[nt].x;
            o.y = acc[nt][1] + xp0[nt].y + bias[nt].y;
            *(float2*)(g_gates + (size_t)b0_ * Gg + nc) = o;
            o.x = acc[nt][2] + xp1[nt].x + bias[nt].x;
            o.y = acc[nt][3] + xp1[nt].y + bias[nt].y;
            *(float2*)(g_gates + (size_t)b1_ * Gg + nc) = o;
        }
        gbar(bg, sh_id, (unsigned)(2 * t + 1));

        // ---- phase B: fused LSTM cell + dual LN for batch j (c resident in SMEM) ----
        if (t < len_j) {
            float* shh = cellf;
            float* scc = cellf + Hh;
            float* red = cellf + 2 * Hh;
            const float* gb = g_gates + (size_t)j * Gg;
            float s0 = 0.f, s1 = 0.f, s2 = 0.f, s3 = 0.f;
            for (int p = tid; p < 384; p += 256) {
                int jj = 2 * p;
                float2 ig = *(const float2*)(gb + jj);
                float2 fg = *(const float2*)(gb + Hh + jj);
                float2 gg = *(const float2*)(gb + 2 * Hh + jj);
                float2 og = *(const float2*)(gb + 3 * Hh + jj);
                float2 cp = *(const float2*)(c_res + jj);
                float cn0, hr0, cn1, hr1;
                cellop(ig.x, fg.x, gg.x, og.x, cp.x, cn0, hr0);
                cellop(ig.y, fg.y, gg.y, og.y, cp.y, cn1, hr1);
                shh[jj] = hr0; shh[jj + 1] = hr1;
                scc[jj] = cn0; scc[jj + 1] = cn1;
                s0 += hr0 + hr1; s1 += hr0 * hr0 + hr1 * hr1;
                s2 += cn0 + cn1; s3 += cn0 * cn0 + cn1 * cn1;
            }
#pragma unroll
            for (int o = 16; o; o >>= 1) {
                s0 += __shfl_down_sync(0xffffffffu, s0, o);
                s1 += __shfl_down_sync(0xffffffffu, s1, o);
                s2 += __shfl_down_sync(0xffffffffu, s2, o);
                s3 += __shfl_down_sync(0xffffffffu, s3, o);
            }
            if (l == 0) { red[w * 4 + 0] = s0; red[w * 4 + 1] = s1; red[w * 4 + 2] = s2; red[w * 4 + 3] = s3; }
            __syncthreads();
            if (tid == 0) {
                float a0 = 0, a1 = 0, a2 = 0, a3 = 0;
                for (int i = 0; i < 8; i++) { a0 += red[4 * i]; a1 += red[4 * i + 1]; a2 += red[4 * i + 2]; a3 += red[4 * i + 3]; }
                red[32] = a0; red[33] = a1; red[34] = a2; red[35] = a3;
            }
            __syncthreads();
            const float inv = 1.0f / 768.0f;
            float muh = red[32] * inv, varh = red[33] * inv - muh * muh;
            float muc = red[34] * inv, varc = red[35] * inv - muc * muc;
            float rsh = rsqrtf(varh + 1e-5f), rsc = rsqrtf(varc + 1e-5f);
            bool last = (t == len_j - 1);
            for (int jj = tid; jj < Hh; jj += 256) {
                float hv = (shh[jj] - muh) * rsh * gmh[jj] + bth[jj];
                float cv = (scc[jj] - muc) * rsc * gmc[jj] + btc[jj];
                g_hpk[(size_t)j * Hh + jj] = pksplit(hv);
                c_res[jj] = cv;
                if (last) out[(size_t)j * Hh + jj] = hv;
            }
        }
        gbar(bg, sh_id, (unsigned)(2 * t + 2));
    }
}

// ---------------- host launcher ----------------
extern "C" void kernel_launch(void* const* d_in, const int* in_sizes, int n_in,
                              void* d_out, int out_size) {
    const int*   msg  = (const int*)d_in[0];
    const int*   mlen = (const int*)d_in[1];
    const float* embt = (const float*)d_in[2];
    const float* Wih  = (const float*)d_in[3];
    const float* Whh  = (const float*)d_in[4];
    const float* bih  = (const float*)d_in[5];
    const float* bhh  = (const float*)d_in[6];
    const float* gmh  = (const float*)d_in[7];
    const float* bth  = (const float*)d_in[8];
    const float* gmc  = (const float*)d_in[9];
    const float* btc  = (const float*)d_in[10];
    float* out = (float*)d_out;

    void* hp; cudaGetSymbolAddress(&hp, g_hpk);
    cudaMemsetAsync(hp, 0, Bb * Hh * sizeof(uint32_t));

    k0_setup<<<1, 256>>>(msg, mlen);
    k1_xproj<<<dim3(64, 48), 256>>>(embt, Wih, bih);

    size_t smem = (size_t)SMEMW * sizeof(uint32_t);  // 218,880 B
    cudaFuncSetAttribute(krec, cudaFuncAttributeMaxDynamicSharedMemorySize, (int)smem);
    krec<<<NCTA, 256, smem>>>(Whh, bhh, gmh, bth, gmc, btc, out);
}

// round 17
// speedup vs baseline: 1.0569x; 1.0569x over previous
#include <cuda_runtime.h>
#include <cuda_bf16.h>
#include <math.h>
#include <stdint.h>

#define Bb 128
#define Tt 64
#define Ee 768
#define Hh 768
#define Gg 3072
#define NCTA 128
#define WPAD 772
#define HPAD2 132                     // h staging row stride (words), 128-word chunks
#define WQ (48 * WPAD)                // W shard words
#define HSBUF (64 * HPAD2)            // per h buffer
#define HSOFF WQ
#define CRES (WQ + 2 * HSBUF)         // resident c (768 floats)
#define SMEMW (CRES + Hh)             // 54,720 words = 218,880 B

__device__ int      g_len[Bb];
__device__ int      g_nrows;
__device__ int      g_rows[Bb * Tt];
__device__ int      g_erow[Bb * Tt];
__device__ float    g_xproj[Tt * Bb * Gg];
__device__ uint32_t g_hpk[Bb * Hh];        // h packed: (lo_bf16<<16)|hi_bf16
__device__ float    g_gates[Bb * Gg];
__device__ unsigned g_bar;

__device__ __forceinline__ uint32_t pksplit(float v) {
    __nv_bfloat16 h = __float2bfloat16(v);
    float r = v - __bfloat162float(h);
    __nv_bfloat16 l = __float2bfloat16(r);
    return ((uint32_t)__bfloat16_as_ushort(l) << 16) | (uint32_t)__bfloat16_as_ushort(h);
}
#define HIPAIR(u0, u1) __byte_perm((u0), (u1), 0x5410)
#define LOPAIR(u0, u1) __byte_perm((u0), (u1), 0x7632)

__device__ __forceinline__ void mma16(float* c, const uint32_t* a, const uint32_t* b) {
    asm volatile("mma.sync.aligned.m16n8k16.row.col.f32.bf16.bf16.f32 "
        "{%0,%1,%2,%3}, {%4,%5,%6,%7}, {%8,%9}, {%0,%1,%2,%3};"
        : "+f"(c[0]), "+f"(c[1]), "+f"(c[2]), "+f"(c[3])
        : "r"(a[0]), "r"(a[1]), "r"(a[2]), "r"(a[3]), "r"(b[0]), "r"(b[1]));
}
__device__ __forceinline__ void cpa16(void* sdst, const void* g) {
    uint32_t sa = (uint32_t)__cvta_generic_to_shared(sdst);
    asm volatile("cp.async.cg.shared.global [%0], [%1], 16;" :: "r"(sa), "l"(g));
}

// FMA-only exp: magic-constant rounding + deg-5 poly for 2^f, |f|<=0.5 (rel err ~3e-6)
// valid for |x| <= ~80 (we clamp to +-25 upstream)
__device__ __forceinline__ float fexp(float x) {
    float y = x * 1.4426950408889634f;
    float t = y + 12582912.0f;                      // round-to-nearest int in mantissa
    int   e = __float_as_int(t) - 0x4B400000;       // integer part
    float f = y - (t - 12582912.0f);                // fractional part in [-0.5, 0.5]
    float p =          1.3397860e-3f;
    p = fmaf(p, f, 9.6146536e-3f);
    p = fmaf(p, f, 5.5504109e-2f);
    p = fmaf(p, f, 2.4022651e-1f);
    p = fmaf(p, f, 6.9314718e-1f);
    p = fmaf(p, f, 1.0f);
    return p * __int_as_float((e + 127) << 23);
}
// FMA-only reciprocal for positive normal x: bit-hack seed + 3 Newton steps (~1e-8 rel)
__device__ __forceinline__ float frcp(float x) {
    float r = __int_as_float(0x7EF311C3 - __float_as_int(x));
    r = r * fmaf(-x, r, 2.0f);
    r = r * fmaf(-x, r, 2.0f);
    r = r * fmaf(-x, r, 2.0f);
    return r;
}

// fused LSTM cell: zero MUFU, all FMA/ALU pipe
__device__ __forceinline__ void cellop(float ig, float fg, float gg, float og,
                                       float c, float& cn, float& hr) {
    ig = fminf(fmaxf(ig, -25.f), 25.f);
    fg = fminf(fmaxf(fg, -25.f), 25.f);
    og = fminf(fmaxf(og, -25.f), 25.f);
    gg = fminf(fmaxf(gg, -12.5f), 12.5f);
    float A  = 1.f + fexp(-ig);
    float F  = 1.f + fexp(-fg);
    float eg = fexp(2.f * gg);
    float AG = A * (eg + 1.f);
    cn = (c * AG + F * (eg - 1.f)) * frcp(F * AG);
    float cc = fminf(fmaxf(cn, -12.5f), 12.5f);
    float e2 = fexp(2.f * cc);
    hr = (e2 - 1.f) * frcp((1.f + fexp(-og)) * (e2 + 1.f));
}

// ---------------- K0: dtype detect + setup (prefix-scan) ----
__global__ void k0_setup(const int* __restrict__ msg, const int* __restrict__ mlen) {
    __shared__ int s_flag;
    __shared__ int s_len[Bb];
    int tid = threadIdx.x;
    if (tid == 0) { s_flag = 0; g_bar = 0; }
    __syncthreads();
    int local = 0;
    for (int i = tid; i < (Bb * Tt) / 2; i += 256)
        if (msg[2 * i + 1] != 0) local = 1;
    if (local) atomicOr(&s_flag, 1);
    __syncthreads();
    int is64 = (s_flag == 0);
    if (tid < Bb) {
        int lb = is64 ? mlen[2 * tid] : mlen[tid];
        g_len[tid] = lb;
        s_len[tid] = lb;
    }
    __syncthreads();
    if (tid < Bb) {
        int base = 0;
        for (int i = 0; i < tid; i++) base += s_len[i];
        int lb = s_len[tid];
        for (int t = 0; t < lb; t++) {
            int r = base + t;
            g_rows[r] = (tid << 6) | t;
            int mi = tid * Tt + t;
            g_erow[r] = is64 ? msg[2 * mi] : msg[mi];
        }
        if (tid == Bb - 1) g_nrows = base + lb;
    }
}

// ---------------- K1: input projection, bf16x3 (proven) ----------
__global__ __launch_bounds__(256) void k1_xproj(const float* __restrict__ embt,
                                                const float* __restrict__ Wih,
                                                const float* __restrict__ bih) {
    __shared__ uint32_t As[128][36];
    __shared__ uint32_t Bs[64][36];
    __shared__ int s_bt[128];
    __shared__ int s_eoff[128];
    int tid = threadIdx.x;
    int nrows = g_nrows;
    int r0 = blockIdx.x * 128;
    if (r0 >= nrows) return;
    int n0 = blockIdx.y * 64;
    if (tid < 128) {
        int r = r0 + tid;
        if (r < nrows) { s_bt[tid] = g_rows[r]; s_eoff[tid] = g_erow[r] * Ee; }
        else           { s_bt[tid] = -1;        s_eoff[tid] = 0; }
    }
    const float* W1 = Wih + (size_t)Gg * Ee;
    int l = tid & 31, w = tid >> 5;
    int wm = w >> 1, wn = w & 1;
    float acc[2][4][4];
#pragma unroll
    for (int i = 0; i < 2; i++)
#pragma unroll
        for (int jn = 0; jn < 4; jn++)
#pragma unroll
            for (int q = 0; q < 4; q++) acc[i][jn][q] = 0.0f;
    int arow = tid >> 1, ak = (tid & 1) * 16;
    int brow = tid >> 2, bk = (tid & 3) * 8;
    for (int kk = 0; kk < Ee; kk += 32) {
        __syncthreads();
        const float* ap = embt + s_eoff[arow] + kk + ak;
#pragma unroll
        for (int i = 0; i < 4; i++) {
            float4 v = *(const float4*)(ap + 4 * i);
            As[arow][ak + 4 * i + 0] = pksplit(v.x);
            As[arow][ak + 4 * i + 1] = pksplit(v.y);
            As[arow][ak + 4 * i + 2] = pksplit(v.z);
            As[arow][ak + 4 * i + 3] = pksplit(v.w);
        }
        const float* bp = W1 + (size_t)(n0 + brow) * Ee + kk + bk;
#pragma unroll
        for (int i = 0; i < 2; i++) {
            float4 v = *(const float4*)(bp + 4 * i);
            Bs[brow][bk + 4 * i + 0] = pksplit(v.x);
            Bs[brow][bk + 4 * i + 1] = pksplit(v.y);
            Bs[brow][bk + 4 * i + 2] = pksplit(v.z);
            Bs[brow][bk + 4 * i + 3] = pksplit(v.w);
        }
        __syncthreads();
#pragma unroll
        for (int k16 = 0; k16 < 2; k16++) {
            int kp = k16 * 16 + (l & 3) * 2;
            uint32_t ahi[2][4], alo[2][4];
#pragma unroll
            for (int mt = 0; mt < 2; mt++) {
                int mb = wm * 32 + mt * 16 + (l >> 2);
                uint2 p0 = *(const uint2*)&As[mb][kp];
                uint2 p1 = *(const uint2*)&As[mb + 8][kp];
                uint2 p2 = *(const uint2*)&As[mb][kp + 8];
                uint2 p3 = *(const uint2*)&As[mb + 8][kp + 8];
                ahi[mt][0] = HIPAIR(p0.x, p0.y); alo[mt][0] = LOPAIR(p0.x, p0.y);
                ahi[mt][1] = HIPAIR(p1.x, p1.y); alo[mt][1] = LOPAIR(p1.x, p1.y);
                ahi[mt][2] = HIPAIR(p2.x, p2.y); alo[mt][2] = LOPAIR(p2.x, p2.y);
                ahi[mt][3] = HIPAIR(p3.x, p3.y); alo[mt][3] = LOPAIR(p3.x, p3.y);
            }
            uint32_t bhi[4][2], blo[4][2];
#pragma unroll
            for (int nt = 0; nt < 4; nt++) {
                int nb = wn * 32 + nt * 8 + (l >> 2);
                uint2 q0 = *(const uint2*)&Bs[nb][kp];
                uint2 q1 = *(const uint2*)&Bs[nb][kp + 8];
                bhi[nt][0] = HIPAIR(q0.x, q0.y); blo[nt][0] = LOPAIR(q0.x, q0.y);
                bhi[nt][1] = HIPAIR(q1.x, q1.y); blo[nt][1] = LOPAIR(q1.x, q1.y);
            }
#pragma unroll
            for (int mt = 0; mt < 2; mt++)
#pragma unroll
                for (int nt = 0; nt < 4; nt++) {
                    mma16(acc[mt][nt], ahi[mt], bhi[nt]);
                    mma16(acc[mt][nt], ahi[mt], blo[nt]);
                    mma16(acc[mt][nt], alo[mt], bhi[nt]);
                }
        }
    }
#pragma unroll
    for (int mt = 0; mt < 2; mt++) {
        int rbase = wm * 32 + mt * 16 + (l >> 2);
#pragma unroll
        for (int nt = 0; nt < 4; nt++) {
            int nc = n0 + wn * 32 + nt * 8 + 2 * (l & 3);
            float2 bias = *(const float2*)(bih + Gg + nc);
            int meta = s_bt[rbase];
            if (meta >= 0) {
                int b_ = meta >> 6, t_ = meta & 63;
                float2 o; o.x = acc[mt][nt][0] + bias.x; o.y = acc[mt][nt][1] + bias.y;
                *(float2*)(g_xproj + ((size_t)(t_ * Bb) + b_) * Gg + nc) = o;
            }
            meta = s_bt[rbase + 8];
            if (meta >= 0) {
                int b_ = meta >> 6, t_ = meta & 63;
                float2 o; o.x = acc[mt][nt][2] + bias.x; o.y = acc[mt][nt][3] + bias.y;
                *(float2*)(g_xproj + ((size_t)(t_ * Bb) + b_) * Gg + nc) = o;
            }
        }
    }
}

// ---------------- persistent recurrence ----------------
// single global 128-CTA barrier — measured-best (rounds 5/11)
__device__ __forceinline__ void grid_sync(unsigned target) {
    __syncthreads();
    if (threadIdx.x == 0) {
        __threadfence();
        atomicAdd(&g_bar, 1u);
        while (*(volatile unsigned*)&g_bar < target) { __nanosleep(64); }
        __threadfence();
    }
    __syncthreads();
}

extern __shared__ uint32_t dsm[];

__global__ __launch_bounds__(256, 1) void krec(
        const float* __restrict__ Whh, const float* __restrict__ bhh,
        const float* __restrict__ gmh, const float* __restrict__ bth,
        const float* __restrict__ gmc, const float* __restrict__ btc,
        float* __restrict__ out) {
    uint32_t* w_sh = dsm;
    uint32_t* hs   = dsm + HSOFF;
    float* cellf   = (float*)(dsm + HSOFF);   // phase-B overlay of h staging
    float* c_res   = (float*)(dsm + CRES);    // resident cell state (this CTA's batch)

    int tid = threadIdx.x;
    int bg = blockIdx.x >> 6;
    int gidx = blockIdx.x & 63;
    int j = blockIdx.x;

    // Load W_hh[1] shard (packed bf16 hi/lo), once for all steps.
    const float* W1 = Whh + (size_t)Gg * Hh + (size_t)gidx * 48 * Hh;
    for (int i = tid; i < 48 * (Hh / 4); i += 256) {
        int n = i / (Hh / 4), kq = (i % (Hh / 4)) * 4;
        float4 v = *(const float4*)(W1 + (size_t)n * Hh + kq);
        uint32_t* d = &w_sh[n * WPAD + kq];
        d[0] = pksplit(v.x); d[1] = pksplit(v.y); d[2] = pksplit(v.z); d[3] = pksplit(v.w);
    }
    // zero resident c
    for (int i = tid; i < Hh; i += 256) c_res[i] = 0.0f;

    int l = tid & 31, w = tid >> 5;
    int wm = w >> 1, wn = w & 1;
    int srow = tid & 63, sq = (tid >> 6) * 32;
    const uint32_t* hsrc_base = g_hpk + (size_t)(bg * 64 + srow) * Hh + sq;
    uint32_t* sd0 = hs + srow * HPAD2 + sq;

    int r_  = wm * 16 + (l >> 2);
    int b0_ = bg * 64 + r_;
    int b1_ = b0_ + 8;
    int len_j = g_len[j];
    unsigned sync_no = 0;
    float2 bias[3];
#pragma unroll
    for (int nt = 0; nt < 3; nt++)
        bias[nt] = *(const float2*)(bhh + Gg + gidx * 48 + wn * 24 + nt * 8 + 2 * (l & 3));

    // preload LN params for this thread's write-loop indices {tid, tid+256, tid+512}
    int j0 = tid, j1 = tid + 256, j2 = tid + 512;
    float gh0 = gmh[j0], gh1 = gmh[j1], gh2 = gmh[j2];
    float bh0 = bth[j0], bh1 = bth[j1], bh2 = bth[j2];
    float gc0 = gmc[j0], gc1 = gmc[j1], gc2 = gmc[j2];
    float bc0 = btc[j0], bc1 = btc[j1], bc2 = btc[j2];

    for (int t = 0; t < Tt; t++) {
        // prefetch xproj (independent of h)
        float2 xp0[3], xp1[3];
#pragma unroll
        for (int nt = 0; nt < 3; nt++) {
            int nc = gidx * 48 + wn * 24 + nt * 8 + 2 * (l & 3);
            xp0[nt] = *(const float2*)(g_xproj + ((size_t)(t * Bb) + b0_) * Gg + nc);
            xp1[nt] = *(const float2*)(g_xproj + ((size_t)(t * Bb) + b1_) * Gg + nc);
        }

        float acc[3][4];
#pragma unroll
        for (int i = 0; i < 3; i++)
#pragma unroll
            for (int q = 0; q < 4; q++) acc[i][q] = 0.0f;

        { // stage chunk 0: 32 words/thread = 8 x 16B cp.async
#pragma unroll
            for (int i = 0; i < 8; i++) cpa16(sd0 + 4 * i, hsrc_base + 4 * i);
            asm volatile("cp.async.commit_group;");
        }
#pragma unroll 1
        for (int c = 0; c < 6; c++) {
            if (c < 5) {
                const uint32_t* src = hsrc_base + (c + 1) * 128;
                uint32_t* dst = sd0 + ((c + 1) & 1) * HSBUF;
#pragma unroll
                for (int i = 0; i < 8; i++) cpa16(dst + 4 * i, src + 4 * i);
                asm volatile("cp.async.commit_group;");
                asm volatile("cp.async.wait_group 1;");
            } else {
                asm volatile("cp.async.wait_group 0;");
            }
            __syncthreads();
            const uint32_t* hb = hs + (c & 1) * HSBUF;
            int ar = wm * 16 + (l >> 2);
#pragma unroll
            for (int k16 = 0; k16 < 8; k16++) {
                int kp = k16 * 16 + (l & 3) * 2;
                uint32_t ahi[4], alo[4];
                {
                    uint2 p0 = *(const uint2*)&hb[ar * HPAD2 + kp];
                    uint2 p1 = *(const uint2*)&hb[(ar + 8) * HPAD2 + kp];
                    uint2 p2 = *(const uint2*)&hb[ar * HPAD2 + kp + 8];
                    uint2 p3 = *(const uint2*)&hb[(ar + 8) * HPAD2 + kp + 8];
                    ahi[0] = HIPAIR(p0.x, p0.y); alo[0] = LOPAIR(p0.x, p0.y);
                    ahi[1] = HIPAIR(p1.x, p1.y); alo[1] = LOPAIR(p1.x, p1.y);
                    ahi[2] = HIPAIR(p2.x, p2.y); alo[2] = LOPAIR(p2.x, p2.y);
                    ahi[3] = HIPAIR(p3.x, p3.y); alo[3] = LOPAIR(p3.x, p3.y);
                }
                int kg = c * 128 + kp;
#pragma unroll
                for (int nt = 0; nt < 3; nt++) {
                    int nr = wn * 24 + nt * 8 + (l >> 2);
                    uint2 q0 = *(const uint2*)&w_sh[nr * WPAD + kg];
                    uint2 q1 = *(const uint2*)&w_sh[nr * WPAD + kg + 8];
                    uint32_t bhi[2], blo[2];
                    bhi[0] = HIPAIR(q0.x, q0.y); blo[0] = LOPAIR(q0.x, q0.y);
                    bhi[1] = HIPAIR(q1.x, q1.y); blo[1] = LOPAIR(q1.x, q1.y);
                    mma16(acc[nt], ahi, bhi);
                    mma16(acc[nt], ahi, blo);
                    mma16(acc[nt], alo, bhi);
                }
            }
            __syncthreads();
        }
        // epilogue: store-only
#pragma unroll
        for (int nt = 0; nt < 3; nt++) {
            int nc = gidx * 48 + wn * 24 + nt * 8 + 2 * (l & 3);
            float2 o;
            o.x = acc[nt][0] + xp0[nt].x + bias[nt].x;
            o.y = acc[nt][1] + xp0[nt].y + bias[nt].y;
            *(float2*)(g_gates + (size_t)b0_ * Gg + nc) = o;
            o.x = acc[nt][2] + xp1[nt].x + bias[nt].x;
            o.y = acc[nt][3] + xp1[nt].y + bias[nt].y;
            *(float2*)(g_gates + (size_t)b1_ * Gg + nc) = o;
        }
        grid_sync(++sync_no * NCTA);

        // ---- phase B: FMA-only LSTM cell + dual LN (c resident in SMEM) ----
        if (t < len_j) {
            float* shh = cellf;
            float* scc = cellf + Hh;
            float* red = cellf + 2 * Hh;
            const float* gb = g_gates + (size_t)j * Gg;
            float s0 = 0.f, s1 = 0.f, s2 = 0.f, s3 = 0.f;
            for (int p = tid; p < 384; p += 256) {
                int jj = 2 * p;
                float2 ig = *(const float2*)(gb + jj);
                float2 fg = *(const float2*)(gb + Hh + jj);
                float2 gg = *(const float2*)(gb + 2 * Hh + jj);
                float2 og = *(const float2*)(gb + 3 * Hh + jj);
                float2 cp = *(const float2*)(c_res + jj);
                float cn0, hr0, cn1, hr1;
                cellop(ig.x, fg.x, gg.x, og.x, cp.x, cn0, hr0);
                cellop(ig.y, fg.y, gg.y, og.y, cp.y, cn1, hr1);
                shh[jj] = hr0; shh[jj + 1] = hr1;
                scc[jj] = cn0; scc[jj + 1] = cn1;
                s0 += hr0 + hr1; s1 += hr0 * hr0 + hr1 * hr1;
                s2 += cn0 + cn1; s3 += cn0 * cn0 + cn1 * cn1;
            }
#pragma unroll
            for (int o = 16; o; o >>= 1) {
                s0 += __shfl_down_sync(0xffffffffu, s0, o);
                s1 += __shfl_down_sync(0xffffffffu, s1, o);
                s2 += __shfl_down_sync(0xffffffffu, s2, o);
                s3 += __shfl_down_sync(0xffffffffu, s3, o);
            }
            if (l == 0) { red[w * 4 + 0] = s0; red[w * 4 + 1] = s1; red[w * 4 + 2] = s2; red[w * 4 + 3] = s3; }
            __syncthreads();
            if (tid == 0) {
                float a0 = 0, a1 = 0, a2 = 0, a3 = 0;
                for (int i = 0; i < 8; i++) { a0 += red[4 * i]; a1 += red[4 * i + 1]; a2 += red[4 * i + 2]; a3 += red[4 * i + 3]; }
                red[32] = a0; red[33] = a1; red[34] = a2; red[35] = a3;
            }
            __syncthreads();
            const float inv = 1.0f / 768.0f;
            float muh = red[32] * inv, varh = red[33] * inv - muh * muh;
            float muc = red[34] * inv, varc = red[35] * inv - muc * muc;
            float rsh = rsqrtf(varh + 1e-5f), rsc = rsqrtf(varc + 1e-5f);
            bool last = (t == len_j - 1);
            {
                float hv0 = (shh[j0] - muh) * rsh * gh0 + bh0;
                float hv1 = (shh[j1] - muh) * rsh * gh1 + bh1;
                float hv2 = (shh[j2] - muh) * rsh * gh2 + bh2;
                float cv0 = (scc[j0] - muc) * rsc * gc0 + bc0;
                float cv1 = (scc[j1] - muc) * rsc * gc1 + bc1;
                float cv2 = (scc[j2] - muc) * rsc * gc2 + bc2;
                g_hpk[(size_t)j * Hh + j0] = pksplit(hv0);
                g_hpk[(size_t)j * Hh + j1] = pksplit(hv1);
                g_hpk[(size_t)j * Hh + j2] = pksplit(hv2);
                c_res[j0] = cv0; c_res[j1] = cv1; c_res[j2] = cv2;
                if (last) {
                    out[(size_t)j * Hh + j0] = hv0;
                    out[(size_t)j * Hh + j1] = hv1;
                    out[(size_t)j * Hh + j2] = hv2;
                }
            }
        }
        grid_sync(++sync_no * NCTA);
    }
}

// ---------------- host launcher ----------------
extern "C" void kernel_launch(void* const* d_in, const int* in_sizes, int n_in,
                              void* d_out, int out_size) {
    const int*   msg  = (const int*)d_in[0];
    const int*   mlen = (const int*)d_in[1];
    const float* embt = (const float*)d_in[2];
    const float* Wih  = (const float*)d_in[3];
    const float* Whh  = (const float*)d_in[4];
    const float* bih  = (const float*)d_in[5];
    const float* bhh  = (const float*)d_in[6];
    const float* gmh  = (const float*)d_in[7];
    const float* bth  = (const float*)d_in[8];
    const float* gmc  = (const float*)d_in[9];
    const float* btc  = (const float*)d_in[10];
    float* out = (float*)d_out;

    void* hp; cudaGetSymbolAddress(&hp, g_hpk);
    cudaMemsetAsync(hp, 0, Bb * Hh * sizeof(uint32_t));

    k0_setup<<<1, 256>>>(msg, mlen);
    k1_xproj<<<dim3(64, 48), 256>>>(embt, Wih, bih);

    size_t smem = (size_t)SMEMW * sizeof(uint32_t);  // 218,880 B
    cudaFuncSetAttribute(krec, cudaFuncAttributeMaxDynamicSharedMemorySize, (int)smem);
    krec<<<NCTA, 256, smem>>>(Whh, bhh, gmh, bth, gmc, btc, out);
}